// round 10
// baseline (speedup 1.0000x reference)
#include <cuda_runtime.h>
#include <math.h>

#define BB 32
#define TT 1024
#define DD 512
#define HH 512
#define HP 516
#define RP 12

// ---------------- scratch (device globals: allocation-free) ----------------
__device__ float g_pre[TT * BB * HH];   // layer-0 input transform + bias, [t][b][j]
__device__ float g_h0[2][BB][HH];       // layer-0 hidden double buffer
__device__ float g_h1[2][BB][HH];       // layer-1 hidden double buffer
__device__ unsigned g_c0[4 * 32];       // per-bg h0 arrival counters (128B apart)
__device__ unsigned g_c1[4 * 32];       // per-bg h1 arrival counters

// ---------------- helpers ----------------------------------------------------
__device__ __forceinline__ unsigned ldacq(const unsigned* p) {
    unsigned v;
    asm volatile("ld.acquire.gpu.u32 %0, [%1];" : "=r"(v) : "l"(p) : "memory");
    return v;
}
__device__ __forceinline__ void red_rel(unsigned* p) {
    asm volatile("red.release.gpu.global.add.u32 [%0], 1;" :: "l"(p) : "memory");
}
__device__ __forceinline__ void fma2(unsigned long long& d,
                                     unsigned long long a, unsigned long long b) {
    asm("fma.rn.f32x2 %0, %1, %2, %0;" : "+l"(d) : "l"(a), "l"(b));
}
__device__ __forceinline__ unsigned long long packf2(float x, float y) {
    return (unsigned long long)__float_as_uint(x)
         | ((unsigned long long)__float_as_uint(y) << 32);
}
#define BARS(id, n) asm volatile("bar.sync %0, %1;" :: "r"(id), "r"(n) : "memory")
#define BARA(id, n) asm volatile("bar.arrive %0, %1;" :: "r"(id), "r"(n) : "memory")

// ---------------- init: zero recurrent state + counters ----------------------
__global__ void init_state() {
    int idx = blockIdx.x * blockDim.x + threadIdx.x;
    if (idx < 2 * BB * HH) {
        ((float*)g_h0)[idx] = 0.f;
        ((float*)g_h1)[idx] = 0.f;
    }
    if (idx < 4 * 32) { g_c0[idx] = 0; g_c1[idx] = 0; }
}

// ---------------- pre-GEMM (layer 0 only), f32x2 packed along k --------------
__global__ __launch_bounds__(256) void gemm_pre(
    const float* __restrict__ X, const float* __restrict__ W,
    const float* __restrict__ b1, const float* __restrict__ b2)
{
    __shared__ unsigned long long As2[8][66];   // [k-pair][m], pair = (2k2, 2k2+1)
    __shared__ unsigned long long Bs2[8][66];

    const int m0 = blockIdx.y * 64;
    const int n0 = blockIdx.x * 64;
    const int tid = threadIdx.x;
    const int r  = tid >> 2;       // 0..63
    const int kq = tid & 3;        // 0..3
    const int tx = tid & 15;
    const int ty = tid >> 4;

    const int m = m0 + r;
    const int t = m >> 5, b = m & 31;
    const float* arow = X + ((size_t)b * TT + t) * DD;
    const float* brow = W + (size_t)(n0 + r) * DD;

    unsigned long long acc2[4][4];
#pragma unroll
    for (int i = 0; i < 4; i++)
#pragma unroll
        for (int j = 0; j < 4; j++) acc2[i][j] = 0ull;

    float4 a_next = *(const float4*)(arow + kq * 4);
    float4 b_next = *(const float4*)(brow + kq * 4);

    for (int kt = 0; kt < DD / 16; kt++) {
        float4 a = a_next, bv = b_next;
        As2[kq * 2 + 0][r] = packf2(a.x, a.y);
        As2[kq * 2 + 1][r] = packf2(a.z, a.w);
        Bs2[kq * 2 + 0][r] = packf2(bv.x, bv.y);
        Bs2[kq * 2 + 1][r] = packf2(bv.z, bv.w);
        __syncthreads();
        if (kt + 1 < DD / 16) {
            a_next = *(const float4*)(arow + (kt + 1) * 16 + kq * 4);
            b_next = *(const float4*)(brow + (kt + 1) * 16 + kq * 4);
        }
#pragma unroll
        for (int k2 = 0; k2 < 8; k2++) {
            ulonglong2 a01 = *(const ulonglong2*)&As2[k2][ty * 4];
            ulonglong2 a23 = *(const ulonglong2*)&As2[k2][ty * 4 + 2];
            ulonglong2 b01 = *(const ulonglong2*)&Bs2[k2][tx * 4];
            ulonglong2 b23 = *(const ulonglong2*)&Bs2[k2][tx * 4 + 2];
            unsigned long long am[4] = {a01.x, a01.y, a23.x, a23.y};
            unsigned long long bn[4] = {b01.x, b01.y, b23.x, b23.y};
#pragma unroll
            for (int i = 0; i < 4; i++)
#pragma unroll
                for (int j = 0; j < 4; j++) fma2(acc2[i][j], am[i], bn[j]);
        }
        __syncthreads();
    }

    float bias[4];
#pragma unroll
    for (int j = 0; j < 4; j++) {
        int n = n0 + tx * 4 + j;
        bias[j] = b1[n] + b2[n];
    }
#pragma unroll
    for (int i = 0; i < 4; i++) {
        int mo = m0 + ty * 4 + i;
        float4 v;
        float s[4];
#pragma unroll
        for (int j = 0; j < 4; j++) {
            unsigned long long acc = acc2[i][j];
            s[j] = __uint_as_float((unsigned)acc)
                 + __uint_as_float((unsigned)(acc >> 32)) + bias[j];
        }
        v.x = s[0]; v.y = s[1]; v.z = s[2]; v.w = s[3];
        *(float4*)&g_pre[(size_t)mo * HH + n0 + tx * 4] = v;
    }
}

// ---------------- warp-specialized fused recurrence --------------------------
// 128 CTAs = 32 j-groups (16 rows) x 4 batch-groups (8 batches). 384 threads.
// G0 (warps 0-3): h0 chain.  G1 (4-7): mat1 + h1 epilogue.  G2 (8-11): mat2.
// Weights permanently in registers (4j x 16k panel per lane).
// Barrier 1: G0 arrives (split-phase), G1 syncs.
// Barrier 7: G1 arrives after its Hs0 reads; G0 syncs before overwriting.
//   G0 PRIMES barrier 7 with one arrive pre-loop so that G0's sync at round r
//   pairs with G1's arrive from round r-1 (acyclic; one round of slack).
#define SMEM_WS ((2*8*HP + 8*HP + 3*128*RP + 128*RP + 32) * 4)

__global__ __launch_bounds__(384, 1) void rnn_ws(
    const float* __restrict__ Whh0, const float* __restrict__ Wih1,
    const float* __restrict__ Whh1, const float* __restrict__ bih1,
    const float* __restrict__ bhh1, float* __restrict__ out)
{
    extern __shared__ float sm[];
    float* Hs0  = sm;                    // 2 bufs x 8 x HP
    float* Hs1  = Hs0 + 2 * 8 * HP;      // 8 x HP
    float* red0 = Hs1 + 8 * HP;          // 128 x RP
    float* red1 = red0 + 128 * RP;       // 128 x RP
    float* red2 = red1 + 128 * RP;       // 2 bufs x 128 x RP
    float* b1s  = red2 + 2 * 128 * RP;   // 16

    const int tid  = threadIdx.x;
    const int wid  = tid >> 5;
    const int lane = tid & 31;
    const int bg = blockIdx.x >> 5;      // 0..3
    const int jg = blockIdx.x & 31;      // 0..31

    const int grp = wid >> 2;            // 0,1,2
    const int w4  = wid & 3;             // warp within group
    const int jq  = lane & 3;
    const int ksl = lane >> 2;           // 0..7
    const int ks  = w4 * 8 + ksl;        // 0..31 k-slice (16 floats)

    // ---- W panel into registers: rows jg*16 + jq*4 + jj, k in [ks*16,+16) ----
    const float* Wsrc = (grp == 0) ? Whh0 : (grp == 1) ? Wih1 : Whh1;
    unsigned long long wreg[4][8];
#pragma unroll
    for (int jj = 0; jj < 4; jj++) {
        const float* wr = Wsrc + (size_t)(jg * 16 + jq * 4 + jj) * HH + ks * 16;
#pragma unroll
        for (int c = 0; c < 8; c++)
            wreg[jj][c] = *(const unsigned long long*)(wr + c * 2);
    }

    // ---- prezero smem tiles / load bias ----
    if (grp == 0) {
        for (int i = tid; i < 2 * 8 * HP; i += 128) Hs0[i] = 0.f;
    } else if (grp == 2) {
        for (int i = tid - 256; i < 8 * HP; i += 128) Hs1[i] = 0.f;
    } else {
        if (tid - 128 < 16) {
            int j = tid - 128;
            b1s[j] = bih1[jg * 16 + j] + bhh1[jg * 16 + j];
        }
    }
    __syncthreads();

    unsigned* cnt0 = &g_c0[bg * 32];
    unsigned* cnt1 = &g_c1[bg * 32];

    const int crow = tid & 127;          // consumer row 0..127
    const int eb = crow >> 4, ej = crow & 15;
    const int gb = bg * 8 + eb;
    const int gj = jg * 16 + ej;
    const size_t HIDOFF = (size_t)BB * TT * HH;

    // =========================== G0: h0 chain ===============================
    if (grp == 0) {
        BARA(7, 256);                     // PRIME barrier 7 (see header comment)
        float pv = g_pre[((size_t)0 * BB + gb) * HH + gj];
        for (int r = 0; r <= TT; r++) {
            float* Hb = Hs0 + (r & 1) * 8 * HP;
            if (r > 0) {
                if (lane == 0) { while (ldacq(cnt0) < (unsigned)(32 * r)) { } }
                __syncwarp();
                if (r >= 2) BARS(7, 256);   // G1 r-1 done => buffer r&1 free
                // stage h0[r-1]
#pragma unroll
                for (int it = 0; it < 8; it++) {
                    int idx = it * 128 + tid;
                    int b = idx >> 7, c = idx & 127;
                    int ph = c ^ ((c >> 2) & 7);
                    *(float4*)&Hb[b * HP + ph * 4] =
                        *(const float4*)&g_h0[(r - 1) & 1][bg * 8 + b][c * 4];
                }
            }
            BARA(1, 256);                 // publish Hs0 to G1 (non-blocking)
            BARS(2, 128);                 // G0-internal: staging visible to G0

            if (r < TT) {
                unsigned long long acc[4][8];
#pragma unroll
                for (int a = 0; a < 4; a++)
#pragma unroll
                    for (int b = 0; b < 8; b++) acc[a][b] = 0ull;
#pragma unroll
                for (int i = 0; i < 4; i++) {
                    int ph = (ks * 4 + i) ^ ksl;
#pragma unroll
                    for (int b = 0; b < 8; b++) {
                        ulonglong2 h2 = *(const ulonglong2*)&Hb[b * HP + ph * 4];
#pragma unroll
                        for (int jj = 0; jj < 4; jj++) {
                            fma2(acc[jj][b], wreg[jj][2 * i],     h2.x);
                            fma2(acc[jj][b], wreg[jj][2 * i + 1], h2.y);
                        }
                    }
                }
                float part[4][8];
#pragma unroll
                for (int jj = 0; jj < 4; jj++)
#pragma unroll
                    for (int b = 0; b < 8; b++) {
                        unsigned long long v = acc[jj][b];
                        part[jj][b] = __uint_as_float((unsigned)v)
                                    + __uint_as_float((unsigned)(v >> 32));
                    }
#pragma unroll
                for (int m = 4; m <= 16; m <<= 1)
#pragma unroll
                    for (int jj = 0; jj < 4; jj++)
#pragma unroll
                        for (int b = 0; b < 8; b++)
                            part[jj][b] += __shfl_xor_sync(0xffffffffu, part[jj][b], m);
                if (ksl == 0) {
#pragma unroll
                    for (int jj = 0; jj < 4; jj++)
#pragma unroll
                        for (int b = 0; b < 8; b++)
                            red0[(b * 16 + jq * 4 + jj) * RP + w4] = part[jj][b];
                }
            }
            BARS(3, 128);                 // red0 ready (G0)
            if (r < TT) {
                float4 p = *(const float4*)&red0[crow * RP];
                float hn = tanhf(pv + p.x + p.y + p.z + p.w);
                g_h0[r & 1][gb][gj] = hn;
                if (r == TT - 1) out[HIDOFF + (size_t)gb * HH + gj] = hn;
                if (r + 1 < TT) pv = g_pre[((size_t)(r + 1) * BB + gb) * HH + gj];
            }
            BARS(8, 128);                 // h0 stores done (G0)
            if (r < TT && tid == 0) red_rel(cnt0);
        }
    }
    // =========================== G1: mat1 + h1 ==============================
    else if (grp == 1) {
        for (int r = 0; r <= TT; r++) {
            float* Hb = Hs0 + (r & 1) * 8 * HP;
            BARS(1, 256);                 // wait Hs0 staged by G0

            unsigned long long acc[4][8];
#pragma unroll
            for (int a = 0; a < 4; a++)
#pragma unroll
                for (int b = 0; b < 8; b++) acc[a][b] = 0ull;
#pragma unroll
            for (int i = 0; i < 4; i++) {
                int ph = (ks * 4 + i) ^ ksl;
#pragma unroll
                for (int b = 0; b < 8; b++) {
                    ulonglong2 h2 = *(const ulonglong2*)&Hb[b * HP + ph * 4];
#pragma unroll
                    for (int jj = 0; jj < 4; jj++) {
                        fma2(acc[jj][b], wreg[jj][2 * i],     h2.x);
                        fma2(acc[jj][b], wreg[jj][2 * i + 1], h2.y);
                    }
                }
            }
            BARA(7, 256);                 // done reading Hs0 buffer r&1

            float part[4][8];
#pragma unroll
            for (int jj = 0; jj < 4; jj++)
#pragma unroll
                for (int b = 0; b < 8; b++) {
                    unsigned long long v = acc[jj][b];
                    part[jj][b] = __uint_as_float((unsigned)v)
                                + __uint_as_float((unsigned)(v >> 32));
                }
#pragma unroll
            for (int m = 4; m <= 16; m <<= 1)
#pragma unroll
                for (int jj = 0; jj < 4; jj++)
#pragma unroll
                    for (int b = 0; b < 8; b++)
                        part[jj][b] += __shfl_xor_sync(0xffffffffu, part[jj][b], m);
            if (ksl == 0) {
#pragma unroll
                for (int jj = 0; jj < 4; jj++)
#pragma unroll
                    for (int b = 0; b < 8; b++)
                        red1[(b * 16 + jq * 4 + jj) * RP + w4] = part[jj][b];
            }
            BARS(4, 256);                 // red1 + red2 ready (G1+G2)
            if (r >= 1) {
                const int t1 = r - 1;
                float4 p1 = *(const float4*)&red1[crow * RP];
                float4 p2 = *(const float4*)&red2[(r & 1) * 128 * RP + crow * RP];
                float hn = tanhf(b1s[ej] + p1.x + p1.y + p1.z + p1.w
                                         + p2.x + p2.y + p2.z + p2.w);
                g_h1[t1 & 1][gb][gj] = hn;
                out[((size_t)gb * TT + t1) * HH + gj] = hn;
                if (t1 == TT - 1)
                    out[HIDOFF + (size_t)BB * HH + (size_t)gb * HH + gj] = hn;
            }
            BARS(5, 128);                 // h1 stores done (G1)
            if (r >= 1 && r < TT && tid == 128) red_rel(cnt1);
        }
    }
    // =========================== G2: mat2 ===================================
    else {
        const int ltid = tid - 256;
        for (int r = 0; r <= TT; r++) {
            if (r >= 2) {
                if (lane == 0) { while (ldacq(cnt1) < (unsigned)(32 * (r - 1))) { } }
                __syncwarp();
                // stage h1[r-2]
#pragma unroll
                for (int it = 0; it < 8; it++) {
                    int idx = it * 128 + ltid;
                    int b = idx >> 7, c = idx & 127;
                    int ph = c ^ ((c >> 2) & 7);
                    *(float4*)&Hs1[b * HP + ph * 4] =
                        *(const float4*)&g_h1[(r - 2) & 1][bg * 8 + b][c * 4];
                }
            }
            BARS(6, 128);                 // Hs1 ready (G2)

            unsigned long long acc[4][8];
#pragma unroll
            for (int a = 0; a < 4; a++)
#pragma unroll
                for (int b = 0; b < 8; b++) acc[a][b] = 0ull;
#pragma unroll
            for (int i = 0; i < 4; i++) {
                int ph = (ks * 4 + i) ^ ksl;
#pragma unroll
                for (int b = 0; b < 8; b++) {
                    ulonglong2 h2 = *(const ulonglong2*)&Hs1[b * HP + ph * 4];
#pragma unroll
                    for (int jj = 0; jj < 4; jj++) {
                        fma2(acc[jj][b], wreg[jj][2 * i],     h2.x);
                        fma2(acc[jj][b], wreg[jj][2 * i + 1], h2.y);
                    }
                }
            }
            float part[4][8];
#pragma unroll
            for (int jj = 0; jj < 4; jj++)
#pragma unroll
                for (int b = 0; b < 8; b++) {
                    unsigned long long v = acc[jj][b];
                    part[jj][b] = __uint_as_float((unsigned)v)
                                + __uint_as_float((unsigned)(v >> 32));
                }
#pragma unroll
            for (int m = 4; m <= 16; m <<= 1)
#pragma unroll
                for (int jj = 0; jj < 4; jj++)
#pragma unroll
                    for (int b = 0; b < 8; b++)
                        part[jj][b] += __shfl_xor_sync(0xffffffffu, part[jj][b], m);
            if (ksl == 0) {
#pragma unroll
                for (int jj = 0; jj < 4; jj++)
#pragma unroll
                    for (int b = 0; b < 8; b++)
                        red2[(r & 1) * 128 * RP + (b * 16 + jq * 4 + jj) * RP + w4]
                            = part[jj][b];
            }
            BARS(4, 256);                 // join G1 (red2 visible)
        }
    }
}

// ---------------- launch ----------------------------------------------------
extern "C" void kernel_launch(void* const* d_in, const int* in_sizes, int n_in,
                              void* d_out, int out_size)
{
    (void)in_sizes; (void)n_in; (void)out_size;
    const float* x    = (const float*)d_in[0];
    const float* wih0 = (const float*)d_in[1];
    const float* whh0 = (const float*)d_in[2];
    const float* bih0 = (const float*)d_in[3];
    const float* bhh0 = (const float*)d_in[4];
    const float* wih1 = (const float*)d_in[5];
    const float* whh1 = (const float*)d_in[6];
    const float* bih1 = (const float*)d_in[7];
    const float* bhh1 = (const float*)d_in[8];
    float* out = (float*)d_out;

    cudaFuncSetAttribute(rnn_ws,
                         cudaFuncAttributeMaxDynamicSharedMemorySize, SMEM_WS);

    init_state<<<128, 256>>>();

    dim3 gemmGrid(HH / 64, (TT * BB) / 64);   // (8, 512)
    gemm_pre<<<gemmGrid, 256>>>(x, wih0, bih0, bhh0);

    rnn_ws<<<128, 384, SMEM_WS>>>(whh0, wih1, whh1, bih1, bhh1, out);
}